// round 13
// baseline (speedup 1.0000x reference)
#include <cuda_runtime.h>
#include <cuda_fp16.h>
#include <cstdint>

#define NTOK  32768          // B*S
#define HDIM  512
#define IDIM  1024
#define NEXP  8
#define NSLOT (2*NTOK)
#define RBLOCKS (NTOK/8)
#define LDP   72             // padded smem stride (halves)
#define MAXT  520            // max token-tiles: sum_e ceil(cnt_e/128) <= 512+8
#define AUXY  64             // extra gateup grid rows for hidden memory work

// ======================= device scratch ======================================
__device__ int   g_cnt[NEXP];        // zeroed by last router block each replay
__device__ int   g_cntro[NEXP];      // snapshot used by GEMM kernels
__device__ int   g_done;             // router-block completion counter (self-resets)
__device__ int   g_list[NEXP*NTOK];
__device__ float g_wt[NSLOT];
__device__ float g_psum[RBLOCKS*NEXP];
__device__ int   g_tilemap[MAXT];
__device__ int   g_ntiles;
__device__ __half g_hs_h[NTOK*HDIM];
__device__ __half g_wg_h[NEXP*IDIM*HDIM];
__device__ __half g_wu_h[NEXP*IDIM*HDIM];
__device__ __half g_wd_h[NEXP*HDIM*IDIM];
__device__ __half g_act_h[67108864];          // NSLOT*IDIM

// ======================= PTX helpers =========================================
__device__ __forceinline__ uint32_t smem_u32(const void* p) {
    uint32_t a;
    asm("{ .reg .u64 t; cvta.to.shared.u64 t, %1; cvt.u32.u64 %0, t; }" : "=r"(a) : "l"(p));
    return a;
}
__device__ __forceinline__ void cpasync16(uint32_t dst, const void* src) {
    asm volatile("cp.async.cg.shared.global [%0], [%1], 16;" :: "r"(dst), "l"(src));
}
#define CP_COMMIT() asm volatile("cp.async.commit_group;" ::: "memory")
#define CP_WAIT1()  asm volatile("cp.async.wait_group 1;" ::: "memory")
#define CP_WAIT0()  asm volatile("cp.async.wait_group 0;" ::: "memory")
__device__ __forceinline__ void ldsm4(uint32_t* r, uint32_t addr) {
    asm volatile("ldmatrix.sync.aligned.m8n8.x4.shared.b16 {%0,%1,%2,%3}, [%4];"
        : "=r"(r[0]), "=r"(r[1]), "=r"(r[2]), "=r"(r[3]) : "r"(addr));
}
// f32-accumulate MMA (the proven fast path on sm_103a legacy HMMA)
__device__ __forceinline__ void mma16816(float* c, uint32_t a0, uint32_t a1,
                                         uint32_t a2, uint32_t a3,
                                         uint32_t b0, uint32_t b1) {
    asm volatile(
        "mma.sync.aligned.m16n8k16.row.col.f32.f16.f16.f32 "
        "{%0,%1,%2,%3}, {%4,%5,%6,%7}, {%8,%9}, {%0,%1,%2,%3};"
        : "+f"(c[0]), "+f"(c[1]), "+f"(c[2]), "+f"(c[3])
        : "r"(a0), "r"(a1), "r"(a2), "r"(a3), "r"(b0), "r"(b1));
}

// ======================= sizes (float4 units) ================================
#define Z4  (NTOK*HDIM/4)                 // out zero region       4,194,304
#define W4  (NEXP*IDIM*HDIM/4)            // one weight tensor     1,048,576
#define PREP_UNITS (2*W4)                 // wg + wu only (serial prep)
#define PREP_BLOCKS ((PREP_UNITS + 511) / 512)
#define AUX_UNITS (Z4 + W4)               // out zeroing + wd convert (hidden)
#define NAUX (AUXY*16)
#define AUX_UPB ((AUX_UNITS + NAUX - 1) / NAUX)
__device__ __forceinline__ void cvt4(const float* src, __half* dst, int u) {
    float4 v = ((const float4*)src)[u];
    __half2 p0 = __floats2half2_rn(v.x, v.y);
    __half2 p1 = __floats2half2_rn(v.z, v.w);
    ((uint2*)dst)[u] = make_uint2(*(uint32_t*)&p0, *(uint32_t*)&p1);
}

// ======================= 1: prep (wg/wu) + router + last-block aux/tilemap ===
__global__ void __launch_bounds__(256) prep_router_kernel(
        const float* __restrict__ hs, const float* __restrict__ wr,
        const float* __restrict__ wg, const float* __restrict__ wu,
        float* __restrict__ out, int out_size) {
    int tid = threadIdx.x;
    if (blockIdx.x < PREP_BLOCKS) {
        int u0 = blockIdx.x * 512 + tid;
#pragma unroll
        for (int r = 0; r < 2; r++) {
            int u = u0 + r*256;
            if (u < W4) {
                cvt4(wg, g_wg_h, u);
            } else if (u < 2*W4) {
                cvt4(wu, g_wu_h, u - W4);
            }
        }
        return;
    }
    // ---------------- router (+ hs fp16 conversion for its 8 rows) ----------
    int rb = blockIdx.x - PREP_BLOCKS;
    __shared__ float swr[NEXP*HDIM];
    __shared__ float sprob[8][NEXP];
    __shared__ int s_islast;
    for (int i = tid; i < NEXP*HDIM; i += 256) swr[i] = wr[i];
    __syncthreads();

    int warp = tid >> 5, lane = tid & 31;
    int t = rb * 8 + warp;
    const float* hrow = hs + (size_t)t * HDIM;

    float acc[NEXP];
#pragma unroll
    for (int e = 0; e < NEXP; e++) acc[e] = 0.f;
    for (int j = lane; j < HDIM; j += 32) {
        float hv = hrow[j];
#pragma unroll
        for (int e = 0; e < NEXP; e++) acc[e] = fmaf(hv, swr[e*HDIM + j], acc[e]);
    }
#pragma unroll
    for (int e = 0; e < NEXP; e++) {
#pragma unroll
        for (int o = 16; o > 0; o >>= 1) acc[e] += __shfl_xor_sync(0xffffffffu, acc[e], o);
    }

    if (lane == 0) {
        int e0 = 0; float v0 = acc[0];
#pragma unroll
        for (int e = 1; e < NEXP; e++) if (acc[e] > v0) { v0 = acc[e]; e0 = e; }
        int e1 = -1; float v1 = -1e30f;
#pragma unroll
        for (int e = 0; e < NEXP; e++) if (e != e0 && acc[e] > v1) { v1 = acc[e]; e1 = e; }

        float z  = __expf(v1 - v0);
        float p1 = z / (1.f + z);
        g_wt[2*t]     = 1.f - p1;
        g_wt[2*t + 1] = p1;

        int pos0 = atomicAdd(&g_cnt[e0], 1);
        g_list[e0*NTOK + pos0] = 2*t;
        int pos1 = atomicAdd(&g_cnt[e1], 1);
        g_list[e1*NTOK + pos1] = 2*t + 1;

        float s = 0.f, pe[NEXP];
#pragma unroll
        for (int e = 0; e < NEXP; e++) { pe[e] = __expf(acc[e] - v0); s += pe[e]; }
        float inv = 1.f / s;
#pragma unroll
        for (int e = 0; e < NEXP; e++) sprob[warp][e] = pe[e] * inv;
    }
    // convert this block's 8 hs rows to fp16 (data is cache-hot)
    {
        const float* base = hs + (size_t)rb * 8 * HDIM;
        __half* dst = g_hs_h + (size_t)rb * 8 * HDIM;
#pragma unroll
        for (int r = 0; r < 4; r++) cvt4(base, dst, tid + r*256);
    }
    __syncthreads();
    if (tid < NEXP) {
        float s = 0.f;
#pragma unroll
        for (int w = 0; w < 8; w++) s += sprob[w][tid];
        g_psum[rb*NEXP + tid] = s;
    }
    // ------------- last-block election: aux loss + tilemap + recycle -------
    __syncthreads();
    if (tid == 0) {
        __threadfence();
        int d = atomicAdd(&g_done, 1);
        s_islast = (d == RBLOCKS - 1) ? 1 : 0;
    }
    __syncthreads();
    if (!s_islast) return;

    // all router blocks' g_psum/g_list/g_wt/g_cnt writes are visible here
    __shared__ float part[256];
    __shared__ int sbase[NEXP+1];
    if (tid < NEXP) { g_cntro[tid] = g_cnt[tid]; g_cnt[tid] = 0; }
    if (tid == 0) g_done = 0;   // reset for next graph replay
    __syncthreads();

    int e = tid & 7, c = tid >> 3;
    const int CH = RBLOCKS / 32;
    float s = 0.f;
    for (int b = c*CH; b < (c+1)*CH; b++) s += g_psum[b*NEXP + e];
    part[tid] = s;
    __syncthreads();
    if (tid < NEXP) {
        float tot = 0.f;
        for (int cc = 0; cc < 32; cc++) tot += part[cc*8 + tid];
        part[tid] = (tot / (float)NTOK) * ((float)g_cntro[tid] / (float)NSLOT) * (float)NEXP;
    }
    __syncthreads();
    if (tid == 0) {
        if (out_size > NTOK*HDIM) {
            float a = 0.f;
#pragma unroll
            for (int ee = 0; ee < NEXP; ee++) a += part[ee];
            out[(size_t)NTOK*HDIM] = a;
        }
        int b = 0;
#pragma unroll
        for (int ee = 0; ee < NEXP; ee++) { sbase[ee] = b; b += (g_cntro[ee] + 127) >> 7; }
        sbase[NEXP] = b;
        g_ntiles = b;
    }
    __syncthreads();
#pragma unroll
    for (int ee = 0; ee < NEXP; ee++) {
        int nt = sbase[ee+1] - sbase[ee];
        for (int tt = tid; tt < nt; tt += 256) g_tilemap[sbase[ee] + tt] = (ee << 16) | tt;
    }
}

// ======================= 2: gate/up GEMM + hidden aux memory work ============
// y < MAXT: GEMM tiles (R8-proven f32-acc path, untouched).
// y >= MAXT: 1024 aux CTAs zero `out` and convert w_down, hidden under the
// MMA-bound GEMM waves (gateup DRAM sits at ~4%).
#define GU_AE  (128*LDP)
#define GU_BE  (64*LDP)
#define GU_STG (GU_AE + 2*GU_BE)
#define GU_SMEM_BYTES (3*GU_STG*2 + 1024)
__global__ void __launch_bounds__(256) gateup_mma_kernel(
        const float* __restrict__ wd, float* __restrict__ out) {
    int y = blockIdx.y;
    int tid = threadIdx.x;
    if (y >= MAXT) {
        // -------- hidden aux: zero out + convert wd --------
        int ai = (y - MAXT) * 16 + blockIdx.x;
        int u0 = ai * AUX_UPB;
        int u1 = u0 + AUX_UPB; if (u1 > AUX_UNITS) u1 = AUX_UNITS;
        for (int u = u0 + tid; u < u1; u += 256) {
            if (u < Z4) ((float4*)out)[u] = make_float4(0.f, 0.f, 0.f, 0.f);
            else        cvt4(wd, g_wd_h, u - Z4);
        }
        return;
    }
    if (y >= g_ntiles) return;
    int tm  = g_tilemap[y];
    int e   = tm >> 16;
    int p0  = (tm & 0xffff) * 128;
    int cnt = g_cntro[e];
    int i0  = blockIdx.x * 64;

    extern __shared__ __half smem[];
    int* s_rowoff = (int*)(smem + 3*GU_STG);
    int* s_slot   = s_rowoff + 128;

    int wid = tid >> 5, lane = tid & 31;
    int wr = wid & 3, wc = wid >> 2;

    if (tid < 128) {
        int p = p0 + tid;
        int cl = (p < cnt) ? p : (cnt - 1);
        int sl = g_list[e*NTOK + cl];
        s_rowoff[tid] = (sl >> 1) * HDIM;
        s_slot[tid]   = (p < cnt) ? sl : -1;
    }
    __syncthreads();
    uint32_t sbase_ = smem_u32(smem);

    auto load_chunk = [&](int c, int st) {
        int k0 = c * 64;
        uint32_t a_s  = sbase_ + st*GU_STG*2;
        uint32_t bg_s = a_s + GU_AE*2;
        uint32_t bu_s = bg_s + GU_BE*2;
#pragma unroll
        for (int it = 0; it < 4; it++) {
            int idx = tid + it*256;
            int row = idx >> 3, v = idx & 7;
            cpasync16(a_s + (row*LDP + v*8)*2, g_hs_h + s_rowoff[row] + k0 + v*8);
        }
#pragma unroll
        for (int it = 0; it < 2; it++) {
            int idx = tid + it*256;
            int row = idx >> 3, v = idx & 7;
            size_t off = ((size_t)e*IDIM + i0 + row) * HDIM + k0 + v*8;
            cpasync16(bg_s + (row*LDP + v*8)*2, g_wg_h + off);
            cpasync16(bu_s + (row*LDP + v*8)*2, g_wu_h + off);
        }
        CP_COMMIT();
    };

    float cg[2][4][4], cu[2][4][4];
#pragma unroll
    for (int m = 0; m < 2; m++)
#pragma unroll
        for (int n = 0; n < 4; n++)
#pragma unroll
            for (int q = 0; q < 4; q++) { cg[m][n][q] = 0.f; cu[m][n][q] = 0.f; }

    int lrow = lane & 7, seg = lane >> 3;
    int rowadd = (seg & 1) ? 8 : 0, coladd = (seg >= 2) ? 8 : 0;   // A form
    int browadd = (seg >= 2) ? 8 : 0, bcoladd = (seg & 1) ? 8 : 0; // B form

    load_chunk(0, 0);
    load_chunk(1, 1);
    for (int c = 0; c < 8; c++) {
        if (c < 7) CP_WAIT1(); else CP_WAIT0();
        __syncthreads();
        if (c + 2 < 8) load_chunk(c + 2, (c + 2) % 3);
        int st = c % 3;
        uint32_t a_s  = sbase_ + st*GU_STG*2;
        uint32_t bg_s = a_s + GU_AE*2;
        uint32_t bu_s = bg_s + GU_BE*2;
#pragma unroll
        for (int kk = 0; kk < 64; kk += 16) {
            uint32_t a[2][4], bg[2][4], bu[2][4];
#pragma unroll
            for (int m = 0; m < 2; m++) {
                int row = wr*32 + m*16 + lrow + rowadd;
                ldsm4(a[m], a_s + (row*LDP + kk + coladd)*2);
            }
#pragma unroll
            for (int j = 0; j < 2; j++) {
                int row = wc*32 + j*16 + lrow + browadd;
                ldsm4(bg[j], bg_s + (row*LDP + kk + bcoladd)*2);
                ldsm4(bu[j], bu_s + (row*LDP + kk + bcoladd)*2);
            }
#pragma unroll
            for (int n = 0; n < 4; n++) {
                int j = n >> 1, s2 = (n & 1) * 2;
#pragma unroll
                for (int m = 0; m < 2; m++) {
                    mma16816(cg[m][n], a[m][0],a[m][1],a[m][2],a[m][3], bg[j][s2], bg[j][s2+1]);
                    mma16816(cu[m][n], a[m][0],a[m][1],a[m][2],a[m][3], bu[j][s2], bu[j][s2+1]);
                }
            }
        }
    }

    // epilogue: act = silu(g)*u -> fp16 by slot
    int g_ = lane >> 2, t_ = lane & 3;
#pragma unroll
    for (int m = 0; m < 2; m++) {
#pragma unroll
        for (int half_ = 0; half_ < 2; half_++) {
            int lr = wr*32 + m*16 + g_ + half_*8;
            int slot = s_slot[lr];
            if (slot < 0) continue;
            __half* oh = g_act_h + (size_t)slot * IDIM + i0 + wc*32;
#pragma unroll
            for (int n = 0; n < 4; n++) {
                float gv0 = cg[m][n][2*half_],   uv0 = cu[m][n][2*half_];
                float gv1 = cg[m][n][2*half_+1], uv1 = cu[m][n][2*half_+1];
                float a0 = (gv0 / (1.f + __expf(-gv0))) * uv0;
                float a1 = (gv1 / (1.f + __expf(-gv1))) * uv1;
                __half2 hp = __floats2half2_rn(a0, a1);
                *(uint32_t*)(oh + n*8 + t_*2) = *(uint32_t*)&hp;
            }
        }
    }
}

// ======================= 3: down GEMM (f32-acc) + fused combine ==============
#define DN_AE  (128*LDP)
#define DN_BE  (128*LDP)
#define DN_STG (DN_AE + DN_BE)
#define DN_SMEM_BYTES (3*DN_STG*2 + 2048)
__global__ void __launch_bounds__(256) down_mma_kernel(float* __restrict__ out) {
    int y = blockIdx.y;
    if (y >= g_ntiles) return;
    int tm  = g_tilemap[y];
    int e   = tm >> 16;
    int p0  = (tm & 0xffff) * 128;
    int cnt = g_cntro[e];
    int h0  = blockIdx.x * 128;

    extern __shared__ __half smem[];
    int*   s_rowoff = (int*)(smem + 3*DN_STG);
    int*   s_slot   = s_rowoff + 128;
    float* s_w      = (float*)(s_slot + 128);

    int tid = threadIdx.x, wid = tid >> 5, lane = tid & 31;
    int wr = wid & 3, wc = wid >> 2;

    if (tid < 128) {
        int p = p0 + tid;
        int cl = (p < cnt) ? p : (cnt - 1);
        int sl = g_list[e*NTOK + cl];
        s_rowoff[tid] = sl * IDIM;
        s_slot[tid]   = (p < cnt) ? sl : -1;
        s_w[tid]      = g_wt[sl];
    }
    __syncthreads();
    uint32_t sbase_ = smem_u32(smem);

    auto load_chunk = [&](int c, int st) {
        int k0 = c * 64;
        uint32_t a_s = sbase_ + st*DN_STG*2;
        uint32_t b_s = a_s + DN_AE*2;
#pragma unroll
        for (int it = 0; it < 4; it++) {
            int idx = tid + it*256;
            int row = idx >> 3, v = idx & 7;
            cpasync16(a_s + (row*LDP + v*8)*2, g_act_h + s_rowoff[row] + k0 + v*8);
        }
#pragma unroll
        for (int it = 0; it < 4; it++) {
            int idx = tid + it*256;
            int row = idx >> 3, v = idx & 7;
            size_t off = ((size_t)e*HDIM + h0 + row) * IDIM + k0 + v*8;
            cpasync16(b_s + (row*LDP + v*8)*2, g_wd_h + off);
        }
        CP_COMMIT();
    };

    float cd[2][8][4];
#pragma unroll
    for (int m = 0; m < 2; m++)
#pragma unroll
        for (int n = 0; n < 8; n++)
#pragma unroll
            for (int q = 0; q < 4; q++) cd[m][n][q] = 0.f;

    int lrow = lane & 7, seg = lane >> 3;
    int rowadd = (seg & 1) ? 8 : 0, coladd = (seg >= 2) ? 8 : 0;
    int browadd = (seg >= 2) ? 8 : 0, bcoladd = (seg & 1) ? 8 : 0;

    load_chunk(0, 0);
    load_chunk(1, 1);
    for (int c = 0; c < 16; c++) {
        if (c < 15) CP_WAIT1(); else CP_WAIT0();
        __syncthreads();
        if (c + 2 < 16) load_chunk(c + 2, (c + 2) % 3);
        int st = c % 3;
        uint32_t a_s = sbase_ + st*DN_STG*2;
        uint32_t b_s = a_s + DN_AE*2;
#pragma unroll
        for (int kk = 0; kk < 64; kk += 16) {
            uint32_t a[2][4], bb[4][4];
#pragma unroll
            for (int m = 0; m < 2; m++) {
                int row = wr*32 + m*16 + lrow + rowadd;
                ldsm4(a[m], a_s + (row*LDP + kk + coladd)*2);
            }
#pragma unroll
            for (int j = 0; j < 4; j++) {
                int row = wc*64 + j*16 + lrow + browadd;
                ldsm4(bb[j], b_s + (row*LDP + kk + bcoladd)*2);
            }
#pragma unroll
            for (int n = 0; n < 8; n++) {
                int j = n >> 1, s2 = (n & 1) * 2;
#pragma unroll
                for (int m = 0; m < 2; m++) {
                    mma16816(cd[m][n], a[m][0],a[m][1],a[m][2],a[m][3], bb[j][s2], bb[j][s2+1]);
                }
            }
        }
    }

    // epilogue: out[token] += w * val (atomic, 2 contributions per element)
    int g_ = lane >> 2, t_ = lane & 3;
#pragma unroll
    for (int m = 0; m < 2; m++) {
#pragma unroll
        for (int half_ = 0; half_ < 2; half_++) {
            int lr = wr*32 + m*16 + g_ + half_*8;
            int slot = s_slot[lr];
            if (slot < 0) continue;
            float w = s_w[lr];
            float* orow = out + (size_t)(slot >> 1) * HDIM + h0 + wc*64;
#pragma unroll
            for (int n = 0; n < 8; n++) {
                atomicAdd(orow + n*8 + t_*2,     w * cd[m][n][2*half_]);
                atomicAdd(orow + n*8 + t_*2 + 1, w * cd[m][n][2*half_+1]);
            }
        }
    }
}

// ======================= launch ==============================================
extern "C" void kernel_launch(void* const* d_in, const int* in_sizes, int n_in,
                              void* d_out, int out_size) {
    const float* hs = (const float*)d_in[0];
    const float* wr = (const float*)d_in[1];
    const float* wg = (const float*)d_in[2];
    const float* wu = (const float*)d_in[3];
    const float* wd = (const float*)d_in[4];
    float* out = (float*)d_out;

    cudaFuncSetAttribute(gateup_mma_kernel, cudaFuncAttributeMaxDynamicSharedMemorySize, GU_SMEM_BYTES);
    cudaFuncSetAttribute(down_mma_kernel,   cudaFuncAttributeMaxDynamicSharedMemorySize, DN_SMEM_BYTES);

    prep_router_kernel<<<PREP_BLOCKS + RBLOCKS, 256>>>(hs, wr, wg, wu, out, out_size);
    gateup_mma_kernel<<<dim3(IDIM/64, MAXT + AUXY, 1), 256, GU_SMEM_BYTES>>>(wd, out);
    down_mma_kernel<<<dim3(HDIM/128, MAXT, 1), 256, DN_SMEM_BYTES>>>(out);
}

// round 14
// speedup vs baseline: 1.0402x; 1.0402x over previous
#include <cuda_runtime.h>
#include <cuda_fp16.h>
#include <cstdint>

#define NTOK  32768          // B*S
#define HDIM  512
#define IDIM  1024
#define NEXP  8
#define NSLOT (2*NTOK)
#define RB2   512            // router blocks (64 tokens each)
#define LDP   72             // padded smem stride (halves)
#define MAXT  520            // max token-tiles: sum_e ceil(cnt_e/128) <= 512+8
#define AUXY  64             // extra gateup grid rows for hidden memory work

// ======================= device scratch ======================================
__device__ int   g_cnt[NEXP];        // zeroed in aux_tilemap for next graph replay
__device__ int   g_cntro[NEXP];      // snapshot used by GEMM kernels
__device__ int   g_list[NEXP*NTOK];
__device__ float g_wt[NSLOT];
__device__ float g_psum[RB2*NEXP];
__device__ int   g_tilemap[MAXT];
__device__ int   g_ntiles;
__device__ __half g_hs_h[NTOK*HDIM];
__device__ __half g_wg_h[NEXP*IDIM*HDIM];
__device__ __half g_wu_h[NEXP*IDIM*HDIM];
__device__ __half g_wd_h[NEXP*HDIM*IDIM];
__device__ __half g_act_h[67108864];          // NSLOT*IDIM

// ======================= PTX helpers =========================================
__device__ __forceinline__ uint32_t smem_u32(const void* p) {
    uint32_t a;
    asm("{ .reg .u64 t; cvta.to.shared.u64 t, %1; cvt.u32.u64 %0, t; }" : "=r"(a) : "l"(p));
    return a;
}
__device__ __forceinline__ void cpasync16(uint32_t dst, const void* src) {
    asm volatile("cp.async.cg.shared.global [%0], [%1], 16;" :: "r"(dst), "l"(src));
}
#define CP_COMMIT() asm volatile("cp.async.commit_group;" ::: "memory")
#define CP_WAIT1()  asm volatile("cp.async.wait_group 1;" ::: "memory")
#define CP_WAIT0()  asm volatile("cp.async.wait_group 0;" ::: "memory")
__device__ __forceinline__ void ldsm4(uint32_t* r, uint32_t addr) {
    asm volatile("ldmatrix.sync.aligned.m8n8.x4.shared.b16 {%0,%1,%2,%3}, [%4];"
        : "=r"(r[0]), "=r"(r[1]), "=r"(r[2]), "=r"(r[3]) : "r"(addr));
}
// f32-accumulate MMA (the proven fast path on sm_103a legacy HMMA)
__device__ __forceinline__ void mma16816(float* c, uint32_t a0, uint32_t a1,
                                         uint32_t a2, uint32_t a3,
                                         uint32_t b0, uint32_t b1) {
    asm volatile(
        "mma.sync.aligned.m16n8k16.row.col.f32.f16.f16.f32 "
        "{%0,%1,%2,%3}, {%4,%5,%6,%7}, {%8,%9}, {%0,%1,%2,%3};"
        : "+f"(c[0]), "+f"(c[1]), "+f"(c[2]), "+f"(c[3])
        : "r"(a0), "r"(a1), "r"(a2), "r"(a3), "r"(b0), "r"(b1));
}

// ======================= sizes (float4 units) ================================
#define Z4  (NTOK*HDIM/4)                 // out zero region       4,194,304
#define W4  (NEXP*IDIM*HDIM/4)            // one weight tensor     1,048,576
#define PREP_BLOCKS2 2048                 // wg: [0,1024), wu: [1024,2048); 1024 units/blk
#define AUX_UNITS (Z4 + W4)               // out zeroing + wd convert (hidden)
#define NAUX (AUXY*16)
#define AUX_UPB ((AUX_UNITS + NAUX - 1) / NAUX)
__device__ __forceinline__ void cvt4(const float* src, __half* dst, int u) {
    float4 v = ((const float4*)src)[u];
    __half2 p0 = __floats2half2_rn(v.x, v.y);
    __half2 p1 = __floats2half2_rn(v.z, v.w);
    ((uint2*)dst)[u] = make_uint2(*(uint32_t*)&p0, *(uint32_t*)&p1);
}

// ======================= 1: prep (wg/wu) + router (64 tok/block) =============
__global__ void __launch_bounds__(256) prep_router_kernel(
        const float* __restrict__ hs, const float* __restrict__ wr,
        const float* __restrict__ wg, const float* __restrict__ wu) {
    int tid = threadIdx.x;
    if (blockIdx.x < PREP_BLOCKS2) {
        int region = blockIdx.x >> 10;            // 0: wg, 1: wu
        int u0 = (blockIdx.x & 1023) * 1024;
        const float* src = region ? wu : wg;
        __half* dst = region ? g_wu_h : g_wg_h;
#pragma unroll
        for (int r = 0; r < 4; r++) cvt4(src, dst, u0 + r*256 + tid);
        return;
    }
    // ---------------- router: 64 tokens per block ---------------------------
    int rb = blockIdx.x - PREP_BLOCKS2;
    int rbase = rb * 64;
    __shared__ float swr[NEXP*HDIM];              // 16 KB
    __shared__ int   s_pick[64];                  // e0 | e1<<8 per token
    __shared__ float sprob[8][NEXP];
    __shared__ int   s_base[NEXP];
    for (int i = tid; i < NEXP*HDIM; i += 256) swr[i] = wr[i];
    __syncthreads();

    int warp = tid >> 5, lane = tid & 31;
    float probacc[NEXP];
#pragma unroll
    for (int e = 0; e < NEXP; e++) probacc[e] = 0.f;

    for (int k = 0; k < 8; k++) {
        int t = rbase + warp*8 + k;
        const float* hrow = hs + (size_t)t * HDIM;
        float acc[NEXP];
#pragma unroll
        for (int e = 0; e < NEXP; e++) acc[e] = 0.f;
        for (int j = lane; j < HDIM; j += 32) {
            float hv = hrow[j];
#pragma unroll
            for (int e = 0; e < NEXP; e++) acc[e] = fmaf(hv, swr[e*HDIM + j], acc[e]);
        }
#pragma unroll
        for (int e = 0; e < NEXP; e++) {
#pragma unroll
            for (int o = 16; o > 0; o >>= 1) acc[e] += __shfl_xor_sync(0xffffffffu, acc[e], o);
        }
        if (lane == 0) {
            int e0 = 0; float v0 = acc[0];
#pragma unroll
            for (int e = 1; e < NEXP; e++) if (acc[e] > v0) { v0 = acc[e]; e0 = e; }
            int e1 = -1; float v1 = -1e30f;
#pragma unroll
            for (int e = 0; e < NEXP; e++) if (e != e0 && acc[e] > v1) { v1 = acc[e]; e1 = e; }

            float z  = __expf(v1 - v0);
            float p1 = z / (1.f + z);
            g_wt[2*t]     = 1.f - p1;
            g_wt[2*t + 1] = p1;
            s_pick[warp*8 + k] = e0 | (e1 << 8);

            float s = 0.f, pe[NEXP];
#pragma unroll
            for (int e = 0; e < NEXP; e++) { pe[e] = __expf(acc[e] - v0); s += pe[e]; }
            float inv = 1.f / s;
#pragma unroll
            for (int e = 0; e < NEXP; e++) probacc[e] += pe[e] * inv;
        }
    }
    if (lane == 0) {
#pragma unroll
        for (int e = 0; e < NEXP; e++) sprob[warp][e] = probacc[e];
    }
    // convert this block's 64 hs rows to fp16 (rows are cache-hot)
    {
        const float* base = hs + (size_t)rbase * HDIM;
        __half* dst = g_hs_h + (size_t)rbase * HDIM;
        for (int u = tid; u < 64*HDIM/4; u += 256) cvt4(base, dst, u);
    }
    __syncthreads();
    // block-aggregated list build: ONE global atomic per expert per block
    if (tid < NEXP) {
        int e = tid;
        int cnt = 0;
#pragma unroll 8
        for (int i = 0; i < 64; i++) {
            int p = s_pick[i];
            cnt += ((p & 255) == e) + ((p >> 8) == e);
        }
        int b = atomicAdd(&g_cnt[e], cnt);
        s_base[e] = b;
        for (int i = 0; i < 64; i++) {
            int p = s_pick[i];
            int slot = 2*(rbase + i);
            if ((p & 255) == e) g_list[e*NTOK + b++] = slot;
            if ((p >> 8) == e)  g_list[e*NTOK + b++] = slot + 1;
        }
        float s = 0.f;
#pragma unroll
        for (int w = 0; w < 8; w++) s += sprob[w][e];
        g_psum[rb*NEXP + e] = s;
    }
}

// ======================= 2: aux loss + tilemap + counter recycle =============
__global__ void aux_tilemap_kernel(float* __restrict__ out, int out_size) {
    __shared__ float part[256];
    __shared__ int sbase[NEXP+1];
    int tid = threadIdx.x;

    if (tid < NEXP) { g_cntro[tid] = g_cnt[tid]; g_cnt[tid] = 0; }
    __syncthreads();

    int e = tid & 7, c = tid >> 3;
    const int CH = RB2 / 32;
    float s = 0.f;
    for (int b = c*CH; b < (c+1)*CH; b++) s += g_psum[b*NEXP + e];
    part[tid] = s;
    __syncthreads();
    if (tid < NEXP) {
        float tot = 0.f;
        for (int cc = 0; cc < 32; cc++) tot += part[cc*8 + tid];
        part[tid] = (tot / (float)NTOK) * ((float)g_cntro[tid] / (float)NSLOT) * (float)NEXP;
    }
    __syncthreads();
    if (tid == 0) {
        if (out_size > NTOK*HDIM) {
            float a = 0.f;
#pragma unroll
            for (int ee = 0; ee < NEXP; ee++) a += part[ee];
            out[(size_t)NTOK*HDIM] = a;
        }
        int b = 0;
#pragma unroll
        for (int ee = 0; ee < NEXP; ee++) { sbase[ee] = b; b += (g_cntro[ee] + 127) >> 7; }
        sbase[NEXP] = b;
        g_ntiles = b;
    }
    __syncthreads();
#pragma unroll
    for (int ee = 0; ee < NEXP; ee++) {
        int nt = sbase[ee+1] - sbase[ee];
        for (int t = tid; t < nt; t += 256) g_tilemap[sbase[ee] + t] = (ee << 16) | t;
    }
}

// ======================= 3: gate/up GEMM + hidden aux memory work ============
#define GU_AE  (128*LDP)
#define GU_BE  (64*LDP)
#define GU_STG (GU_AE + 2*GU_BE)
#define GU_SMEM_BYTES (3*GU_STG*2 + 1024)
__global__ void __launch_bounds__(256) gateup_mma_kernel(
        const float* __restrict__ wd, float* __restrict__ out) {
    int y = blockIdx.y;
    int tid = threadIdx.x;
    if (y >= MAXT) {
        // -------- hidden aux: zero out + convert wd --------
        int ai = (y - MAXT) * 16 + blockIdx.x;
        int u0 = ai * AUX_UPB;
        int u1 = u0 + AUX_UPB; if (u1 > AUX_UNITS) u1 = AUX_UNITS;
        for (int u = u0 + tid; u < u1; u += 256) {
            if (u < Z4) ((float4*)out)[u] = make_float4(0.f, 0.f, 0.f, 0.f);
            else        cvt4(wd, g_wd_h, u - Z4);
        }
        return;
    }
    if (y >= g_ntiles) return;
    int tm  = g_tilemap[y];
    int e   = tm >> 16;
    int p0  = (tm & 0xffff) * 128;
    int cnt = g_cntro[e];
    int i0  = blockIdx.x * 64;

    extern __shared__ __half smem[];
    int* s_rowoff = (int*)(smem + 3*GU_STG);
    int* s_slot   = s_rowoff + 128;

    int wid = tid >> 5, lane = tid & 31;
    int wr = wid & 3, wc = wid >> 2;

    if (tid < 128) {
        int p = p0 + tid;
        int cl = (p < cnt) ? p : (cnt - 1);
        int sl = g_list[e*NTOK + cl];
        s_rowoff[tid] = (sl >> 1) * HDIM;
        s_slot[tid]   = (p < cnt) ? sl : -1;
    }
    __syncthreads();
    uint32_t sbase_ = smem_u32(smem);

    auto load_chunk = [&](int c, int st) {
        int k0 = c * 64;
        uint32_t a_s  = sbase_ + st*GU_STG*2;
        uint32_t bg_s = a_s + GU_AE*2;
        uint32_t bu_s = bg_s + GU_BE*2;
#pragma unroll
        for (int it = 0; it < 4; it++) {
            int idx = tid + it*256;
            int row = idx >> 3, v = idx & 7;
            cpasync16(a_s + (row*LDP + v*8)*2, g_hs_h + s_rowoff[row] + k0 + v*8);
        }
#pragma unroll
        for (int it = 0; it < 2; it++) {
            int idx = tid + it*256;
            int row = idx >> 3, v = idx & 7;
            size_t off = ((size_t)e*IDIM + i0 + row) * HDIM + k0 + v*8;
            cpasync16(bg_s + (row*LDP + v*8)*2, g_wg_h + off);
            cpasync16(bu_s + (row*LDP + v*8)*2, g_wu_h + off);
        }
        CP_COMMIT();
    };

    float cg[2][4][4], cu[2][4][4];
#pragma unroll
    for (int m = 0; m < 2; m++)
#pragma unroll
        for (int n = 0; n < 4; n++)
#pragma unroll
            for (int q = 0; q < 4; q++) { cg[m][n][q] = 0.f; cu[m][n][q] = 0.f; }

    int lrow = lane & 7, seg = lane >> 3;
    int rowadd = (seg & 1) ? 8 : 0, coladd = (seg >= 2) ? 8 : 0;   // A form
    int browadd = (seg >= 2) ? 8 : 0, bcoladd = (seg & 1) ? 8 : 0; // B form

    load_chunk(0, 0);
    load_chunk(1, 1);
    for (int c = 0; c < 8; c++) {
        if (c < 7) CP_WAIT1(); else CP_WAIT0();
        __syncthreads();
        if (c + 2 < 8) load_chunk(c + 2, (c + 2) % 3);
        int st = c % 3;
        uint32_t a_s  = sbase_ + st*GU_STG*2;
        uint32_t bg_s = a_s + GU_AE*2;
        uint32_t bu_s = bg_s + GU_BE*2;
#pragma unroll
        for (int kk = 0; kk < 64; kk += 16) {
            uint32_t a[2][4], bg[2][4], bu[2][4];
#pragma unroll
            for (int m = 0; m < 2; m++) {
                int row = wr*32 + m*16 + lrow + rowadd;
                ldsm4(a[m], a_s + (row*LDP + kk + coladd)*2);
            }
#pragma unroll
            for (int j = 0; j < 2; j++) {
                int row = wc*32 + j*16 + lrow + browadd;
                ldsm4(bg[j], bg_s + (row*LDP + kk + bcoladd)*2);
                ldsm4(bu[j], bu_s + (row*LDP + kk + bcoladd)*2);
            }
#pragma unroll
            for (int n = 0; n < 4; n++) {
                int j = n >> 1, s2 = (n & 1) * 2;
#pragma unroll
                for (int m = 0; m < 2; m++) {
                    mma16816(cg[m][n], a[m][0],a[m][1],a[m][2],a[m][3], bg[j][s2], bg[j][s2+1]);
                    mma16816(cu[m][n], a[m][0],a[m][1],a[m][2],a[m][3], bu[j][s2], bu[j][s2+1]);
                }
            }
        }
    }

    // epilogue: act = silu(g)*u -> fp16 by slot
    int g_ = lane >> 2, t_ = lane & 3;
#pragma unroll
    for (int m = 0; m < 2; m++) {
#pragma unroll
        for (int half_ = 0; half_ < 2; half_++) {
            int lr = wr*32 + m*16 + g_ + half_*8;
            int slot = s_slot[lr];
            if (slot < 0) continue;
            __half* oh = g_act_h + (size_t)slot * IDIM + i0 + wc*32;
#pragma unroll
            for (int n = 0; n < 4; n++) {
                float gv0 = cg[m][n][2*half_],   uv0 = cu[m][n][2*half_];
                float gv1 = cg[m][n][2*half_+1], uv1 = cu[m][n][2*half_+1];
                float a0 = (gv0 / (1.f + __expf(-gv0))) * uv0;
                float a1 = (gv1 / (1.f + __expf(-gv1))) * uv1;
                __half2 hp = __floats2half2_rn(a0, a1);
                *(uint32_t*)(oh + n*8 + t_*2) = *(uint32_t*)&hp;
            }
        }
    }
}

// ======================= 4: down GEMM (f32-acc) + fused combine ==============
#define DN_AE  (128*LDP)
#define DN_BE  (128*LDP)
#define DN_STG (DN_AE + DN_BE)
#define DN_SMEM_BYTES (3*DN_STG*2 + 2048)
__global__ void __launch_bounds__(256) down_mma_kernel(float* __restrict__ out) {
    int y = blockIdx.y;
    if (y >= g_ntiles) return;
    int tm  = g_tilemap[y];
    int e   = tm >> 16;
    int p0  = (tm & 0xffff) * 128;
    int cnt = g_cntro[e];
    int h0  = blockIdx.x * 128;

    extern __shared__ __half smem[];
    int*   s_rowoff = (int*)(smem + 3*DN_STG);
    int*   s_slot   = s_rowoff + 128;
    float* s_w      = (float*)(s_slot + 128);

    int tid = threadIdx.x, wid = tid >> 5, lane = tid & 31;
    int wr = wid & 3, wc = wid >> 2;

    if (tid < 128) {
        int p = p0 + tid;
        int cl = (p < cnt) ? p : (cnt - 1);
        int sl = g_list[e*NTOK + cl];
        s_rowoff[tid] = sl * IDIM;
        s_slot[tid]   = (p < cnt) ? sl : -1;
        s_w[tid]      = g_wt[sl];
    }
    __syncthreads();
    uint32_t sbase_ = smem_u32(smem);

    auto load_chunk = [&](int c, int st) {
        int k0 = c * 64;
        uint32_t a_s = sbase_ + st*DN_STG*2;
        uint32_t b_s = a_s + DN_AE*2;
#pragma unroll
        for (int it = 0; it < 4; it++) {
            int idx = tid + it*256;
            int row = idx >> 3, v = idx & 7;
            cpasync16(a_s + (row*LDP + v*8)*2, g_act_h + s_rowoff[row] + k0 + v*8);
        }
#pragma unroll
        for (int it = 0; it < 4; it++) {
            int idx = tid + it*256;
            int row = idx >> 3, v = idx & 7;
            size_t off = ((size_t)e*HDIM + h0 + row) * IDIM + k0 + v*8;
            cpasync16(b_s + (row*LDP + v*8)*2, g_wd_h + off);
        }
        CP_COMMIT();
    };

    float cd[2][8][4];
#pragma unroll
    for (int m = 0; m < 2; m++)
#pragma unroll
        for (int n = 0; n < 8; n++)
#pragma unroll
            for (int q = 0; q < 4; q++) cd[m][n][q] = 0.f;

    int lrow = lane & 7, seg = lane >> 3;
    int rowadd = (seg & 1) ? 8 : 0, coladd = (seg >= 2) ? 8 : 0;
    int browadd = (seg >= 2) ? 8 : 0, bcoladd = (seg & 1) ? 8 : 0;

    load_chunk(0, 0);
    load_chunk(1, 1);
    for (int c = 0; c < 16; c++) {
        if (c < 15) CP_WAIT1(); else CP_WAIT0();
        __syncthreads();
        if (c + 2 < 16) load_chunk(c + 2, (c + 2) % 3);
        int st = c % 3;
        uint32_t a_s = sbase_ + st*DN_STG*2;
        uint32_t b_s = a_s + DN_AE*2;
#pragma unroll
        for (int kk = 0; kk < 64; kk += 16) {
            uint32_t a[2][4], bb[4][4];
#pragma unroll
            for (int m = 0; m < 2; m++) {
                int row = wr*32 + m*16 + lrow + rowadd;
                ldsm4(a[m], a_s + (row*LDP + kk + coladd)*2);
            }
#pragma unroll
            for (int j = 0; j < 4; j++) {
                int row = wc*64 + j*16 + lrow + browadd;
                ldsm4(bb[j], b_s + (row*LDP + kk + bcoladd)*2);
            }
#pragma unroll
            for (int n = 0; n < 8; n++) {
                int j = n >> 1, s2 = (n & 1) * 2;
#pragma unroll
                for (int m = 0; m < 2; m++) {
                    mma16816(cd[m][n], a[m][0],a[m][1],a[m][2],a[m][3], bb[j][s2], bb[j][s2+1]);
                }
            }
        }
    }

    // epilogue: out[token] += w * val (atomic, 2 contributions per element)
    int g_ = lane >> 2, t_ = lane & 3;
#pragma unroll
    for (int m = 0; m < 2; m++) {
#pragma unroll
        for (int half_ = 0; half_ < 2; half_++) {
            int lr = wr*32 + m*16 + g_ + half_*8;
            int slot = s_slot[lr];
            if (slot < 0) continue;
            float w = s_w[lr];
            float* orow = out + (size_t)(slot >> 1) * HDIM + h0 + wc*64;
#pragma unroll
            for (int n = 0; n < 8; n++) {
                atomicAdd(orow + n*8 + t_*2,     w * cd[m][n][2*half_]);
                atomicAdd(orow + n*8 + t_*2 + 1, w * cd[m][n][2*half_+1]);
            }
        }
    }
}

// ======================= launch ==============================================
extern "C" void kernel_launch(void* const* d_in, const int* in_sizes, int n_in,
                              void* d_out, int out_size) {
    const float* hs = (const float*)d_in[0];
    const float* wr = (const float*)d_in[1];
    const float* wg = (const float*)d_in[2];
    const float* wu = (const float*)d_in[3];
    const float* wd = (const float*)d_in[4];
    float* out = (float*)d_out;

    cudaFuncSetAttribute(gateup_mma_kernel, cudaFuncAttributeMaxDynamicSharedMemorySize, GU_SMEM_BYTES);
    cudaFuncSetAttribute(down_mma_kernel,   cudaFuncAttributeMaxDynamicSharedMemorySize, DN_SMEM_BYTES);

    prep_router_kernel<<<PREP_BLOCKS2 + RB2, 256>>>(hs, wr, wg, wu);
    aux_tilemap_kernel<<<1, 256>>>(out, out_size);
    gateup_mma_kernel<<<dim3(IDIM/64, MAXT + AUXY, 1), 256, GU_SMEM_BYTES>>>(wd, out);
    down_mma_kernel<<<dim3(HDIM/128, MAXT, 1), 256, DN_SMEM_BYTES>>>(out);
}